// round 12
// baseline (speedup 1.0000x reference)
#include <cuda_runtime.h>
#include <cuda_bf16.h>
#include <cstdint>

#define BDIM 8192      // batch
#define DDIM 768       // model dim
#define FDIM 24576     // dict size
#define KTOP 64        // top-k
#define KSEL 128       // candidate pool for fp64 re-ranking

// ---------------- device scratch ---------------------------------------------
__device__ __nv_bfloat16 g_post[(size_t)BDIM * FDIM];  // post-ReLU preacts (bf16)
__device__ float g_cenc[FDIM];                  // b_enc[n] - dot(b_dec, W_enc[n,:])
__device__ int   g_topi96[BDIM * KSEL];
__device__ float g_topv[BDIM * KTOP];
__device__ int   g_topi[BDIM * KTOP];
__device__ float g_wdt[(size_t)FDIM * DDIM];    // W_dec transposed -> [F, D]
__device__ __nv_bfloat16 g_xb[(size_t)BDIM * DDIM];  // X in bf16
__device__ __nv_bfloat16 g_wb[(size_t)FDIM * DDIM];  // W_enc in bf16

// ---------------- kernel 0: fold biases --------------------------------------
__global__ void cenc_kernel(const float* __restrict__ W,
                            const float* __restrict__ be,
                            const float* __restrict__ bd) {
    int gw = (blockIdx.x * blockDim.x + threadIdx.x) >> 5;
    int lane = threadIdx.x & 31;
    if (gw >= FDIM) return;
    const float* wr = W + (size_t)gw * DDIM;
    float s = 0.f;
    for (int k = lane; k < DDIM; k += 32) s += bd[k] * wr[k];
    #pragma unroll
    for (int o = 16; o; o >>= 1) s += __shfl_xor_sync(0xffffffffu, s, o);
    if (lane == 0) g_cenc[gw] = be[gw] - s;
}

// ---------------- bf16 conversion kernels ------------------------------------
__global__ void cvt_x_kernel(const float* __restrict__ s) {
    size_t i = ((size_t)blockIdx.x * 256 + threadIdx.x) * 4;
    float4 v = *(const float4*)(s + i);
    *(__nv_bfloat162*)(g_xb + i)     = __floats2bfloat162_rn(v.x, v.y);
    *(__nv_bfloat162*)(g_xb + i + 2) = __floats2bfloat162_rn(v.z, v.w);
}
__global__ void cvt_w_kernel(const float* __restrict__ s) {
    size_t i = ((size_t)blockIdx.x * 256 + threadIdx.x) * 4;
    float4 v = *(const float4*)(s + i);
    *(__nv_bfloat162*)(g_wb + i)     = __floats2bfloat162_rn(v.x, v.y);
    *(__nv_bfloat162*)(g_wb + i + 2) = __floats2bfloat162_rn(v.z, v.w);
}

// ---------------- kernel 1: W_dec transpose [D,F] -> [F,D] -------------------
__global__ void transpose_kernel(const float* __restrict__ wd) {
    __shared__ float tile[32][33];
    int bx = blockIdx.x, by = blockIdx.y;
    int tx = threadIdx.x, ty = threadIdx.y;     // 32 x 8
    int f = bx * 32 + tx;
    #pragma unroll
    for (int j = 0; j < 32; j += 8)
        tile[ty + j][tx] = wd[(size_t)(by * 32 + ty + j) * FDIM + f];
    __syncthreads();
    int d = by * 32 + tx;
    #pragma unroll
    for (int j = 0; j < 32; j += 8)
        g_wdt[(size_t)(bx * 32 + ty + j) * DDIM + d] = tile[tx][ty + j];
}

// ---------------- kernel 2: encode GEMM (bf16 mma.sync m16n8k16) -------------
// 4-stage cp.async pipeline; bf16 output (candidate-pool precision only;
// refine_kernel provides exact values/selection).
#define BK     32                 // K per tile (bf16)
#define STR    40                 // smem row stride in bf16 (80B, conflict-free)
#define TILEE  (128 * STR)        // bf16 elements per buffer (5120)
#define TILEB  (TILEE * 2)        // bytes per buffer (10240)
#define NSTAGE 4
#define GSMEM  (NSTAGE * TILEB * 2)   // 81920 bytes

__device__ __forceinline__ void cp16(uint32_t dst, const void* src) {
    asm volatile("cp.async.cg.shared.global [%0], [%1], 16;\n"
                 :: "r"(dst), "l"(src) : "memory");
}
__device__ __forceinline__ void ldmx4(uint32_t* r, uint32_t addr) {
    asm volatile("ldmatrix.sync.aligned.m8n8.x4.shared.b16 {%0,%1,%2,%3}, [%4];\n"
                 : "=r"(r[0]), "=r"(r[1]), "=r"(r[2]), "=r"(r[3]) : "r"(addr));
}
__device__ __forceinline__ void mma_bf16(float* c, const uint32_t* a,
                                         uint32_t b0, uint32_t b1) {
    asm volatile("mma.sync.aligned.m16n8k16.row.col.f32.bf16.bf16.f32 "
                 "{%0,%1,%2,%3}, {%4,%5,%6,%7}, {%8,%9}, {%0,%1,%2,%3};\n"
                 : "+f"(c[0]), "+f"(c[1]), "+f"(c[2]), "+f"(c[3])
                 : "r"(a[0]), "r"(a[1]), "r"(a[2]), "r"(a[3]), "r"(b0), "r"(b1));
}

__global__ __launch_bounds__(256, 2)
void gemm_bf16_kernel() {
    extern __shared__ __align__(16) char smem[];
    __nv_bfloat16* sAe = (__nv_bfloat16*)smem;
    __nv_bfloat16* sBe = (__nv_bfloat16*)(smem + NSTAGE * TILEB);

    const int t = threadIdx.x;
    const int L = t & 31, w = t >> 5;
    const int wm = w & 1, wn = w >> 1;         // warp tile: rows wm*64, cols wn*32
    const int m0 = blockIdx.y * 128, n0 = blockIdx.x * 128;

    // ---- staging: thread t covers row (t>>1), 32B half (t&1) of each matrix --
    const int srow = t >> 1, soff = (t & 1) * 16;
    const uint32_t aBase = (uint32_t)__cvta_generic_to_shared(sAe);
    const uint32_t bBase = (uint32_t)__cvta_generic_to_shared(sBe);
    const uint32_t sOff = (uint32_t)(srow * STR + soff) * 2u;
    const __nv_bfloat16* aSrc = g_xb + (size_t)(m0 + srow) * DDIM + soff;
    const __nv_bfloat16* bSrc = g_wb + (size_t)(n0 + srow) * DDIM + soff;

    // ---- fragment addresses ----
    const int aRow = wm * 64 + (L & 15);
    const uint32_t aFragBase = aBase + (uint32_t)(aRow * STR + (L >> 4) * 8) * 2u;
    const int bN = wn * 32 + (L >> 2);
    const int bK = 2 * (L & 3);

    float acc[4][4][4];
    #pragma unroll
    for (int mt = 0; mt < 4; mt++)
        #pragma unroll
        for (int nt = 0; nt < 4; nt++)
            #pragma unroll
            for (int r = 0; r < 4; r++) acc[mt][nt][r] = 0.f;

    #define STAGE(chunk, buf) do {                                        \
        const uint32_t bo_ = (uint32_t)((buf) * TILEB) + sOff;            \
        const int kt_ = (chunk) * BK;                                     \
        cp16(aBase + bo_,       aSrc + kt_);                              \
        cp16(aBase + bo_ + 16u, aSrc + kt_ + 8);                          \
        cp16(bBase + bo_,       bSrc + kt_);                              \
        cp16(bBase + bo_ + 16u, bSrc + kt_ + 8);                          \
        asm volatile("cp.async.commit_group;\n" ::: "memory");            \
    } while (0)

    // ---- prologue: stage tiles 0..2 ----
    STAGE(0, 0);
    STAGE(1, 1);
    STAGE(2, 2);

    const int NIT = DDIM / BK;   // 24
    for (int it = 0; it < NIT; ++it) {
        const int buf = it & (NSTAGE - 1);
        asm volatile("cp.async.wait_group 2;\n" ::: "memory");
        __syncthreads();
        if (it + 3 < NIT) STAGE(it + 3, (it + 3) & (NSTAGE - 1));

        const uint32_t aB = aFragBase + (uint32_t)(buf * TILEB);
        const __nv_bfloat16* bS = &sBe[(size_t)buf * TILEE + bN * STR + bK];
        #pragma unroll
        for (int k16 = 0; k16 < 2; k16++) {
            uint32_t a[4][4];
            #pragma unroll
            for (int mt = 0; mt < 4; mt++)
                ldmx4(a[mt], aB + (uint32_t)(mt * 16 * STR + k16 * 16) * 2u);
            uint32_t b0[4], b1[4];
            #pragma unroll
            for (int nt = 0; nt < 4; nt++) {
                const __nv_bfloat16* bp = bS + nt * 8 * STR + k16 * 16;
                b0[nt] = *(const uint32_t*)bp;
                b1[nt] = *(const uint32_t*)(bp + 8);
            }
            #pragma unroll
            for (int mt = 0; mt < 4; mt++)
                #pragma unroll
                for (int nt = 0; nt < 4; nt++)
                    mma_bf16(acc[mt][nt], a[mt], b0[nt], b1[nt]);
        }
    }
    #undef STAGE

    // ---- epilogue: + cenc, ReLU, store bf16 pairs ----
    const int g = L >> 2, tig = L & 3;
    #pragma unroll
    for (int nt = 0; nt < 4; nt++) {
        const int n = n0 + wn * 32 + nt * 8 + 2 * tig;
        const float2 ce = *(const float2*)&g_cenc[n];
        #pragma unroll
        for (int mt = 0; mt < 4; mt++) {
            const int m = m0 + wm * 64 + mt * 16 + g;
            __nv_bfloat162 v0 = __floats2bfloat162_rn(
                fmaxf(acc[mt][nt][0] + ce.x, 0.f), fmaxf(acc[mt][nt][1] + ce.y, 0.f));
            __nv_bfloat162 v1 = __floats2bfloat162_rn(
                fmaxf(acc[mt][nt][2] + ce.x, 0.f), fmaxf(acc[mt][nt][3] + ce.y, 0.f));
            *(__nv_bfloat162*)&g_post[(size_t)m * FDIM + n]       = v0;
            *(__nv_bfloat162*)&g_post[(size_t)(m + 8) * FDIM + n] = v1;
        }
    }
}

// ---------------- kernel 3: per-row top-128 (2-scan histogram select) --------
#define NCAND 1024

__global__ void topk_kernel() {
    const int row = blockIdx.x;
    const unsigned short* __restrict__ p =
        (const unsigned short*)(g_post + (size_t)row * FDIM);
    const int t = threadIdx.x, lane = t & 31;

    __shared__ unsigned hist[4096];
    __shared__ unsigned csum[256];
    __shared__ int s_tbin;
    __shared__ unsigned s_cnt;
    __shared__ unsigned skey[NCAND];
    __shared__ int      sidx[NCAND];

    if (t == 0) s_cnt = 0u;
    #pragma unroll
    for (int j = 0; j < 16; j++) hist[t + 256 * j] = 0u;
    __syncthreads();

    // pass 1: 4096-bin histogram of bf16 bits >> 4 (values >= 0)
    for (int i = t; i < FDIM; i += 256) {
        unsigned key = p[i];
        if (key == 0x8000u) key = 0u;          // -0 guard
        const unsigned bin = key >> 4;
        const unsigned m = __match_any_sync(0xffffffffu, bin);
        if (lane == (__ffs(m) - 1)) atomicAdd(&hist[bin], __popc(m));
    }
    __syncthreads();

    // descending chunk sums, then serial threshold-bin search
    {
        const int base = 4096 - 16 * (t + 1);
        unsigned cs = 0;
        #pragma unroll
        for (int j = 0; j < 16; j++) cs += hist[base + j];
        csum[t] = cs;
    }
    __syncthreads();
    if (t == 0) {
        unsigned cum = 0;
        int c = 0;
        while (cum + csum[c] < KSEL) { cum += csum[c]; c++; }
        int bin = 4096 - 16 * c - 1;
        while (cum + hist[bin] < KSEL) { cum += hist[bin]; bin--; }
        s_tbin = bin;
    }
    __syncthreads();
    const unsigned tb = (unsigned)s_tbin;

    // pass 2: collect all candidates in bins >= tb
    for (int i = t; i < FDIM; i += 256) {
        unsigned key = p[i];
        if (key == 0x8000u) key = 0u;
        if ((key >> 4) >= tb) {
            unsigned pos = atomicAdd(&s_cnt, 1u);
            if (pos < NCAND) { skey[pos] = key; sidx[pos] = i; }
        }
    }
    __syncthreads();
    const int n = (int)min(s_cnt, (unsigned)NCAND);

    // rank (value desc, index asc) and emit top-KSEL indices
    for (int s = t; s < n; s += 256) {
        const unsigned k = skey[s];
        const int id = sidx[s];
        int r = 0;
        for (int j = 0; j < n; j++) {
            const unsigned kj = skey[j];
            r += (kj > k) || (kj == k && sidx[j] < id);
        }
        if (r < KSEL) g_topi96[row * KSEL + r] = id;
    }
}

// ---------------- kernel 3b: fp64 re-rank of the candidates ------------------
__global__ __launch_bounds__(256, 4)
void refine_kernel(const float* __restrict__ X, const float* __restrict__ W) {
    const int row = blockIdx.x;
    const int t = threadIdx.x, lane = t & 31, w = t >> 5;   // 8 warps

    __shared__ float sx[DDIM];
    __shared__ double s_val[KSEL];
    __shared__ int    s_idx[KSEL];

    for (int i = t; i < DDIM; i += 256) sx[i] = X[(size_t)row * DDIM + i];
    if (t < KSEL) s_idx[t] = g_topi96[row * KSEL + t];
    __syncthreads();

    for (int j = w; j < KSEL; j += 8) {
        const float* wr = W + (size_t)s_idx[j] * DDIM;
        double s = 0.0;
        for (int k = lane; k < DDIM; k += 32)
            s = fma((double)sx[k], (double)wr[k], s);
        #pragma unroll
        for (int o = 16; o; o >>= 1) s += __shfl_xor_sync(0xffffffffu, s, o);
        if (lane == 0) s_val[j] = s + (double)g_cenc[s_idx[j]];
    }
    __syncthreads();

    if (t < KSEL) {
        const double mv = s_val[t];
        const int    mi = s_idx[t];
        int r = 0;
        for (int j = 0; j < KSEL; j++) {
            const double v = s_val[j];
            r += (v > mv) || (v == mv && s_idx[j] < mi);
        }
        if (r < KTOP) {
            g_topv[row * KTOP + r] = (float)mv;   // fp64-accurate value
            g_topi[row * KTOP + r] = mi;
        }
    }
}

// ---------------- kernel 4: sparse decode ------------------------------------
__global__ void decode_kernel(const float* __restrict__ b_dec,
                              float* __restrict__ out) {
    const int row = blockIdx.x;
    const int t = threadIdx.x;
    __shared__ float sv0[KTOP];
    __shared__ int   si0[KTOP];
    __shared__ float sv[KTOP];
    __shared__ int   si[KTOP];
    if (t < KTOP) {
        sv0[t] = g_topv[row * KTOP + t];
        si0[t] = g_topi[row * KTOP + t];
    }
    __syncthreads();
    if (t < KTOP) {              // sort by index ascending (indices unique)
        const int my = si0[t];
        int r = 0;
        #pragma unroll 8
        for (int j = 0; j < KTOP; j++) r += (si0[j] < my);
        si[r] = my;
        sv[r] = sv0[t];
    }
    __syncthreads();
    float a0 = 0.f, a1 = 0.f, a2 = 0.f;
    #pragma unroll 4
    for (int k = 0; k < KTOP; k++) {
        const float v = sv[k];
        const float* wv = g_wdt + (size_t)si[k] * DDIM;
        a0 = fmaf(v, wv[t],       a0);
        a1 = fmaf(v, wv[t + 256], a1);
        a2 = fmaf(v, wv[t + 512], a2);
    }
    float* o = out + (size_t)row * DDIM;
    o[t]       = a0 + b_dec[t];
    o[t + 256] = a1 + b_dec[t + 256];
    o[t + 512] = a2 + b_dec[t + 512];
}

// ---------------- host entry --------------------------------------------------
extern "C" void kernel_launch(void* const* d_in, const int* in_sizes, int n_in,
                              void* d_out, int out_size) {
    const float* x     = (const float*)d_in[0];   // [B, D]
    const float* W_enc = (const float*)d_in[1];   // [F, D]
    const float* b_enc = (const float*)d_in[2];   // [F]
    const float* W_dec = (const float*)d_in[3];   // [D, F]
    const float* b_dec = (const float*)d_in[4];   // [D]
    float* out = (float*)d_out;                   // [B, D]

    cudaFuncSetAttribute(gemm_bf16_kernel,
                         cudaFuncAttributeMaxDynamicSharedMemorySize, GSMEM);

    cenc_kernel<<<FDIM * 32 / 256, 256>>>(W_enc, b_enc, b_dec);
    cvt_x_kernel<<<(BDIM * DDIM) / 1024, 256>>>(x);
    cvt_w_kernel<<<(FDIM * DDIM) / 1024, 256>>>(W_enc);
    transpose_kernel<<<dim3(FDIM / 32, DDIM / 32), dim3(32, 8)>>>(W_dec);
    gemm_bf16_kernel<<<dim3(FDIM / 128, BDIM / 128), 256, GSMEM>>>();
    topk_kernel<<<BDIM, 256>>>();
    refine_kernel<<<BDIM, 256>>>(x, W_enc);
    decode_kernel<<<BDIM, 256>>>(b_dec, out);
}